// round 4
// baseline (speedup 1.0000x reference)
#include <cuda_runtime.h>
#include <cstdint>
#include <cstddef>

// CSPN_6468220748336 — deep cp.async pipeline version (resubmit after infra flake).
// out[b,y,x] = sum_{i,j} gw[b, i*7+j, y+3, x+3] * src[b, y+3-i, x+3-j]
//   src = h0 at (i,j)=(3,3), else hn; zero-padded outside [0,512)^2.
// gw is streamed tap-by-tap into SMEM via cp.async.cg (16B chunks, aligned-down),
// keeping 6 stages (~26KB/block) of DRAM reads in flight independent of registers.

namespace {
constexpr int K  = 7;
constexpr int K2 = 49;
constexpr int H  = 512;
constexpr int W  = 512;
constexpr int WP = 518;
constexpr int PLANE = WP * WP;

constexpr int BX = 128;                 // output cols per block
constexpr int BY = 8;                   // output rows per block (1 warp/row)
constexpr int NT = 256;

constexpr int DEPTH = 6;                // cp.async groups kept in flight
constexpr int NSLOT = 8;                // ring slots (read->overwrite separated by 2 barriers)
constexpr int CHUNKS = 34;              // 16B chunks per staged row (136 floats)
constexpr int SPITCH = CHUNKS * 4;      // 136 floats per staged row
constexpr int STAGE  = BY * SPITCH;     // 1088 floats per slot

constexpr int TW = 140;                 // hn halo tile cols [X0-3, X0+137)
constexpr int TH = 14;                  // hn halo tile rows [Y0-3, Y0+11)
}

__device__ __forceinline__ void issue_chunk(
    const float* __restrict__ gw, size_t base0, int t2, int slot, int c,
    float (*s_gw)[STAGE])
{
    const int r = c / CHUNKS;
    const int k = c - r * CHUNKS;
    const char* src = (const char*)(gw + base0 + (size_t)t2 * PLANE + (size_t)r * WP);
    src = (const char*)(((uintptr_t)src) & ~(uintptr_t)15) + 16 * k;
    const uint32_t dst =
        (uint32_t)__cvta_generic_to_shared(&s_gw[slot][r * SPITCH + 4 * k]);
    asm volatile("cp.async.cg.shared.global [%0], [%1], 16;" :: "r"(dst), "l"(src));
}

__global__ __launch_bounds__(NT, 5) void cspn_kernel(
    const float* __restrict__ gw,
    const float* __restrict__ hn,
    const float* __restrict__ h0,
    float* __restrict__ out)
{
    __shared__ __align__(16) float s_gw[NSLOT][STAGE];   // 34816 B
    __shared__ float s_hn[TH][TW];                       //  7840 B

    const int b   = blockIdx.z;
    const int X0  = blockIdx.x * BX;
    const int Y0  = blockIdx.y * BY;
    const int tid = threadIdx.x;
    const int w   = tid >> 5;
    const int l   = tid & 31;

    // float index of gw[b, tap0, Y0+3, X0+3]; row r adds r*WP, tap t adds t*PLANE
    const size_t base0 = (size_t)b * K2 * PLANE + (size_t)(Y0 + 3) * WP + (X0 + 3);

    // ---- prologue: issue stages 0..DEPTH-1 ----
    #pragma unroll
    for (int t2 = 0; t2 < DEPTH; ++t2) {
        const int slot = t2 & (NSLOT - 1);
        issue_chunk(gw, base0, t2, slot, tid, s_gw);
        if (tid < BY * CHUNKS - NT)
            issue_chunk(gw, base0, t2, slot, tid + NT, s_gw);
        asm volatile("cp.async.commit_group;" ::);
    }

    // ---- stage hn halo tile (overlaps with in-flight cp.async) ----
    const float* __restrict__ hnb = hn + (size_t)b * H * W;
    #pragma unroll
    for (int idx = tid; idx < TH * TW; idx += NT) {
        const int r  = idx / TW;
        const int cc = idx - r * TW;
        const int gy = Y0 - 3 + r;
        const int gx = X0 - 3 + cc;
        float v = 0.0f;
        if ((unsigned)gy < (unsigned)H && (unsigned)gx < (unsigned)W)
            v = __ldg(hnb + (size_t)gy * W + gx);
        s_hn[r][cc] = v;
    }

    // per-row alignment phase: p in {1,3}, d = 4-p in {3,1}
    const int p  = (((Y0 + w + 3) * WP) + X0 + 3) & 3;
    const int d  = 4 - p;
    const int x0 = X0 + 4 * l + d;                 // first owned output col
    const int y  = Y0 + w;

    const float* __restrict__ h0row = h0 + ((size_t)b * H + y) * W;
    float* __restrict__ orow = out + ((size_t)b * H + y) * W;

    float h0v[4];
    #pragma unroll
    for (int m = 0; m < 4; ++m)
        h0v[m] = (x0 + m < W) ? __ldg(h0row + x0 + m) : 0.0f;

    __syncthreads();    // publish s_hn

    float a0 = 0.f, a1 = 0.f, a2 = 0.f, a3 = 0.f;
    const int gidx = w * SPITCH + 4 * l + 4;       // p+4l+d == 4l+4, row-parity invariant

    #pragma unroll 1
    for (int i = 0; i < K; ++i) {
        // hn window for this tap-row: wv[q] = s_hn[w+6-i][4l+d+q]
        const float* hr = &s_hn[w + 6 - i][4 * l + d];
        float wv[10];
        #pragma unroll
        for (int q = 0; q < 10; ++q) wv[q] = hr[q];

        #pragma unroll
        for (int j = 0; j < K; ++j) {
            const int t  = i * K + j;
            const int t2 = t + DEPTH;
            if (t2 < K2) {
                const int slot = t2 & (NSLOT - 1);
                issue_chunk(gw, base0, t2, slot, tid, s_gw);
                if (tid < BY * CHUNKS - NT)
                    issue_chunk(gw, base0, t2, slot, tid + NT, s_gw);
            }
            asm volatile("cp.async.commit_group;" ::);          // empty groups in tail keep FIFO accounting
            asm volatile("cp.async.wait_group %0;" :: "n"(DEPTH));
            __syncthreads();

            const float4 g =
                *reinterpret_cast<const float4*>(&s_gw[t & (NSLOT - 1)][gidx]);
            const bool ctr = (i == 3) && (j == 3);
            a0 = fmaf(g.x, ctr ? h0v[0] : wv[6 - j + 0], a0);
            a1 = fmaf(g.y, ctr ? h0v[1] : wv[6 - j + 1], a1);
            a2 = fmaf(g.z, ctr ? h0v[2] : wv[6 - j + 2], a2);
            a3 = fmaf(g.w, ctr ? h0v[3] : wv[6 - j + 3], a3);
        }
    }

    if (x0 + 0 < W) orow[x0 + 0] = a0;
    if (x0 + 1 < W) orow[x0 + 1] = a1;
    if (x0 + 2 < W) orow[x0 + 2] = a2;
    if (x0 + 3 < W) orow[x0 + 3] = a3;

    // ---- left-edge outputs x in [0, d), leftmost blocks only ----
    if (X0 == 0 && l < d) {
        const float h0e = __ldg(h0row + l);
        float acc = 0.0f;
        #pragma unroll
        for (int i2 = 0; i2 < K; ++i2) {
            #pragma unroll
            for (int j2 = 0; j2 < K; ++j2) {
                const float g = __ldg(gw + base0 + (size_t)(i2 * K + j2) * PLANE
                                         + (size_t)w * WP + l);
                const float v = (i2 == 3 && j2 == 3) ? h0e
                                                     : s_hn[w + 6 - i2][l + 6 - j2];
                acc = fmaf(g, v, acc);
            }
        }
        orow[l] = acc;
    }
}

extern "C" void kernel_launch(void* const* d_in, const int* in_sizes, int n_in,
                              void* d_out, int out_size)
{
    const float* gw = (const float*)d_in[0];
    const float* hn = (const float*)d_in[1];
    const float* h0 = (const float*)d_in[2];
    float* out = (float*)d_out;

    dim3 block(NT, 1, 1);
    dim3 grid(W / BX, H / BY, 8);
    cspn_kernel<<<grid, block>>>(gw, hn, h0, out);
}

// round 5
// speedup vs baseline: 1.1712x; 1.1712x over previous
#include <cuda_runtime.h>
#include <cstddef>
#include <cstdint>

// CSPN_6468220748336 — R2 (vectorized ownership-shift) + explicit register
// double-buffer prefetch across tap-rows + streaming stores.
// out[b,y,x] = sum_{i,j} gw[b, i*7+j, y+3, x+3] * src[b, y+3-i, x+3-j]
//   src = h0 at (i,j)=(3,3), else hn; zero-padded outside [0,512)^2.

namespace {
constexpr int K  = 7;
constexpr int K2 = 49;
constexpr int B  = 8;
constexpr int H  = 512;
constexpr int W  = 512;
constexpr int WP = 518;
constexpr int PLANE = WP * WP;

constexpr int BX = 128;
constexpr int BY = 8;
constexpr int NT = 256;

constexpr int TILE_W = 140;
constexpr int TILE_H = 14;
}

template <int D>
__device__ __forceinline__ void row_compute(
    const float* __restrict__ p0,        // aligned float4 base, tap 0 (this lane)
    const float (*__restrict__ s_hn)[TILE_W],
    const float* __restrict__ h0_row,
    float* __restrict__ out_row,
    int X0, int w, int l)
{
    const int x0 = X0 + 4 * l + D;

    float h0v[4];
    #pragma unroll
    for (int m = 0; m < 4; ++m)
        h0v[m] = (x0 + m < W) ? __ldg(h0_row + x0 + m) : 0.0f;

    float a0 = 0.f, a1 = 0.f, a2 = 0.f, a3 = 0.f;

    // ---- software pipeline: g holds current tap-row, gn prefetches next ----
    float4 g[K];
    #pragma unroll
    for (int j = 0; j < K; ++j)
        g[j] = __ldcs(reinterpret_cast<const float4*>(p0 + (size_t)j * PLANE));

    #pragma unroll
    for (int i = 0; i < K; ++i) {
        float4 gn[K];
        if (i < K - 1) {
            #pragma unroll
            for (int j = 0; j < K; ++j)
                gn[j] = __ldcs(reinterpret_cast<const float4*>(
                                   p0 + (size_t)((i + 1) * K + j) * PLANE));
        }

        const int r = w + 6 - i;
        const float4 wa = *reinterpret_cast<const float4*>(&s_hn[r][4 * l]);
        const float4 wb = *reinterpret_cast<const float4*>(&s_hn[r][4 * l + 4]);
        const float4 wc = *reinterpret_cast<const float4*>(&s_hn[r][4 * l + 8]);
        const float4 wd = *reinterpret_cast<const float4*>(&s_hn[r][4 * l + 12]);
        const float win[16] = {wa.x, wa.y, wa.z, wa.w, wb.x, wb.y, wb.z, wb.w,
                               wc.x, wc.y, wc.z, wc.w, wd.x, wd.y, wd.z, wd.w};

        #pragma unroll
        for (int j = 0; j < K; ++j) {
            if (i == 3 && j == 3) {
                a0 = fmaf(g[j].x, h0v[0], a0);
                a1 = fmaf(g[j].y, h0v[1], a1);
                a2 = fmaf(g[j].z, h0v[2], a2);
                a3 = fmaf(g[j].w, h0v[3], a3);
            } else {
                a0 = fmaf(g[j].x, win[D + 0 + 6 - j], a0);
                a1 = fmaf(g[j].y, win[D + 1 + 6 - j], a1);
                a2 = fmaf(g[j].z, win[D + 2 + 6 - j], a2);
                a3 = fmaf(g[j].w, win[D + 3 + 6 - j], a3);
            }
        }

        if (i < K - 1) {
            #pragma unroll
            for (int j = 0; j < K; ++j) g[j] = gn[j];
        }
    }

    if (x0 + 0 < W) __stcs(out_row + x0 + 0, a0);
    if (x0 + 1 < W) __stcs(out_row + x0 + 1, a1);
    if (x0 + 2 < W) __stcs(out_row + x0 + 2, a2);
    if (x0 + 3 < W) __stcs(out_row + x0 + 3, a3);
}

__global__ __launch_bounds__(NT) void cspn_kernel(
    const float* __restrict__ gw,
    const float* __restrict__ hn,
    const float* __restrict__ h0,
    float* __restrict__ out)
{
    __shared__ __align__(16) float s_hn[TILE_H][TILE_W];

    const int b  = blockIdx.z;
    const int X0 = blockIdx.x * BX;
    const int Y0 = blockIdx.y * BY;
    const int tid = threadIdx.x;
    const int w = tid >> 5;
    const int l = tid & 31;

    // ---- stage hn halo tile (zero-padded) ----
    const float* __restrict__ hn_b = hn + (size_t)b * H * W;
    #pragma unroll
    for (int idx = tid; idx < TILE_H * TILE_W; idx += NT) {
        const int r  = idx / TILE_W;
        const int c  = idx - r * TILE_W;
        const int gy = Y0 - 3 + r;
        const int gx = X0 - 3 + c;
        float v = 0.0f;
        if ((unsigned)gy < (unsigned)H && (unsigned)gx < (unsigned)W)
            v = __ldg(hn_b + (size_t)gy * W + gx);
        s_hn[r][c] = v;
    }
    __syncthreads();

    const int y = Y0 + w;
    const float* __restrict__ gw_b = gw + (size_t)b * K2 * PLANE;
    const float* rowp = gw_b + (size_t)(y + 3) * WP + 3 + X0;
    const int d = (int)((16u - ((uint32_t)(uintptr_t)rowp & 15u)) >> 2) & 3;  // 1 or 3

    const float* p0 = rowp + 4 * l + d;  // 16B-aligned
    const float* h0_row = h0 + ((size_t)b * H + y) * W;
    float* out_row = out + ((size_t)b * H + y) * W;

    if (d == 3)
        row_compute<3>(p0, s_hn, h0_row, out_row, X0, w, l);
    else
        row_compute<1>(p0, s_hn, h0_row, out_row, X0, w, l);

    // ---- left-edge outputs x in [0, d), leftmost blocks only ----
    if (X0 == 0 && l < d) {
        const int xe = l;
        const float h0e = __ldg(h0_row + xe);
        float acc = 0.0f;
        #pragma unroll
        for (int i = 0; i < K; ++i) {
            #pragma unroll
            for (int j = 0; j < K; ++j) {
                const float g = __ldcs(gw_b + (size_t)(i * K + j) * PLANE
                                       + (size_t)(y + 3) * WP + (xe + 3));
                const float v = (i == 3 && j == 3) ? h0e : s_hn[w + 6 - i][xe + 6 - j];
                acc = fmaf(g, v, acc);
            }
        }
        __stcs(out_row + xe, acc);
    }
}

extern "C" void kernel_launch(void* const* d_in, const int* in_sizes, int n_in,
                              void* d_out, int out_size)
{
    const float* gw = (const float*)d_in[0];
    const float* hn = (const float*)d_in[1];
    const float* h0 = (const float*)d_in[2];
    float* out = (float*)d_out;

    dim3 block(NT, 1, 1);
    dim3 grid(W / BX, H / BY, B);
    cspn_kernel<<<grid, block>>>(gw, hn, h0, out);
}

// round 6
// speedup vs baseline: 1.1718x; 1.0005x over previous
#include <cuda_runtime.h>
#include <cstddef>
#include <cstdint>

// CSPN_6468220748336 — vectorized ownership-shift + static ring-buffer prefetch
// (lookahead Q=8, compile-time indices) + 3 CTAs/SM occupancy target.
// out[b,y,x] = sum_{i,j} gw[b, i*7+j, y+3, x+3] * src[b, y+3-i, x+3-j]
//   src = h0 at (i,j)=(3,3), else hn; zero-padded outside [0,512)^2.

namespace {
constexpr int K  = 7;
constexpr int K2 = 49;
constexpr int B  = 8;
constexpr int H  = 512;
constexpr int W  = 512;
constexpr int WP = 518;
constexpr int PLANE = WP * WP;

constexpr int BX = 128;
constexpr int BY = 8;
constexpr int NT = 256;

constexpr int Q  = 8;                  // prefetch lookahead (taps), ring size

constexpr int TILE_W = 140;
constexpr int TILE_H = 14;
}

template <int D>
__device__ __forceinline__ void row_compute(
    const float* __restrict__ p0,        // aligned float4 base, tap 0 (this lane)
    const float (*__restrict__ s_hn)[TILE_W],
    const float* __restrict__ h0_row,
    float* __restrict__ out_row,
    int X0, int w, int l)
{
    const int x0 = X0 + 4 * l + D;

    float h0v[4];
    #pragma unroll
    for (int m = 0; m < 4; ++m)
        h0v[m] = (x0 + m < W) ? __ldg(h0_row + x0 + m) : 0.0f;

    float a0 = 0.f, a1 = 0.f, a2 = 0.f, a3 = 0.f;

    // ---- ring prefetch: taps 0..Q-1 in flight before compute starts ----
    float4 gbuf[Q];
    #pragma unroll
    for (int q = 0; q < Q; ++q)
        gbuf[q] = __ldcs(reinterpret_cast<const float4*>(p0 + (size_t)q * PLANE));

    float win[16];

    #pragma unroll
    for (int t = 0; t < K2; ++t) {
        const int i = t / K;
        const int j = t - i * K;

        if (j == 0) {
            // refresh hn window for tap-row i (4 conflict-free LDS.128)
            const int r = w + 6 - i;
            const float4 wa = *reinterpret_cast<const float4*>(&s_hn[r][4 * l]);
            const float4 wb = *reinterpret_cast<const float4*>(&s_hn[r][4 * l + 4]);
            const float4 wc = *reinterpret_cast<const float4*>(&s_hn[r][4 * l + 8]);
            const float4 wd = *reinterpret_cast<const float4*>(&s_hn[r][4 * l + 12]);
            win[0] = wa.x;  win[1] = wa.y;  win[2]  = wa.z;  win[3]  = wa.w;
            win[4] = wb.x;  win[5] = wb.y;  win[6]  = wb.z;  win[7]  = wb.w;
            win[8] = wc.x;  win[9] = wc.y;  win[10] = wc.z;  win[11] = wc.w;
            win[12] = wd.x; win[13] = wd.y; win[14] = wd.z;  win[15] = wd.w;
        }

        const float4 g = gbuf[t % Q];
        // immediately refill this ring slot with tap t+Q (keeps >=Q-1 in flight)
        if (t + Q < K2)
            gbuf[t % Q] = __ldcs(reinterpret_cast<const float4*>(
                                     p0 + (size_t)(t + Q) * PLANE));

        if (i == 3 && j == 3) {
            a0 = fmaf(g.x, h0v[0], a0);
            a1 = fmaf(g.y, h0v[1], a1);
            a2 = fmaf(g.z, h0v[2], a2);
            a3 = fmaf(g.w, h0v[3], a3);
        } else {
            a0 = fmaf(g.x, win[D + 0 + 6 - j], a0);
            a1 = fmaf(g.y, win[D + 1 + 6 - j], a1);
            a2 = fmaf(g.z, win[D + 2 + 6 - j], a2);
            a3 = fmaf(g.w, win[D + 3 + 6 - j], a3);
        }
    }

    if (x0 + 0 < W) __stcs(out_row + x0 + 0, a0);
    if (x0 + 1 < W) __stcs(out_row + x0 + 1, a1);
    if (x0 + 2 < W) __stcs(out_row + x0 + 2, a2);
    if (x0 + 3 < W) __stcs(out_row + x0 + 3, a3);
}

__global__ __launch_bounds__(NT, 3) void cspn_kernel(
    const float* __restrict__ gw,
    const float* __restrict__ hn,
    const float* __restrict__ h0,
    float* __restrict__ out)
{
    __shared__ __align__(16) float s_hn[TILE_H][TILE_W];

    const int b  = blockIdx.z;
    const int X0 = blockIdx.x * BX;
    const int Y0 = blockIdx.y * BY;
    const int tid = threadIdx.x;
    const int w = tid >> 5;
    const int l = tid & 31;

    // ---- stage hn halo tile (zero-padded) ----
    const float* __restrict__ hn_b = hn + (size_t)b * H * W;
    #pragma unroll
    for (int idx = tid; idx < TILE_H * TILE_W; idx += NT) {
        const int r  = idx / TILE_W;
        const int c  = idx - r * TILE_W;
        const int gy = Y0 - 3 + r;
        const int gx = X0 - 3 + c;
        float v = 0.0f;
        if ((unsigned)gy < (unsigned)H && (unsigned)gx < (unsigned)W)
            v = __ldg(hn_b + (size_t)gy * W + gx);
        s_hn[r][c] = v;
    }
    __syncthreads();

    const int y = Y0 + w;
    const float* __restrict__ gw_b = gw + (size_t)b * K2 * PLANE;
    const float* rowp = gw_b + (size_t)(y + 3) * WP + 3 + X0;
    const int d = (int)((16u - ((uint32_t)(uintptr_t)rowp & 15u)) >> 2) & 3;  // 1 or 3

    const float* p0 = rowp + 4 * l + d;  // 16B-aligned
    const float* h0_row = h0 + ((size_t)b * H + y) * W;
    float* out_row = out + ((size_t)b * H + y) * W;

    if (d == 3)
        row_compute<3>(p0, s_hn, h0_row, out_row, X0, w, l);
    else
        row_compute<1>(p0, s_hn, h0_row, out_row, X0, w, l);

    // ---- left-edge outputs x in [0, d), leftmost blocks only ----
    if (X0 == 0 && l < d) {
        const int xe = l;
        const float h0e = __ldg(h0_row + xe);
        float acc = 0.0f;
        #pragma unroll
        for (int i = 0; i < K; ++i) {
            #pragma unroll
            for (int j = 0; j < K; ++j) {
                const float g = __ldcs(gw_b + (size_t)(i * K + j) * PLANE
                                       + (size_t)(y + 3) * WP + (xe + 3));
                const float v = (i == 3 && j == 3) ? h0e : s_hn[w + 6 - i][xe + 6 - j];
                acc = fmaf(g, v, acc);
            }
        }
        __stcs(out_row + xe, acc);
    }
}

extern "C" void kernel_launch(void* const* d_in, const int* in_sizes, int n_in,
                              void* d_out, int out_size)
{
    const float* gw = (const float*)d_in[0];
    const float* hn = (const float*)d_in[1];
    const float* h0 = (const float*)d_in[2];
    float* out = (float*)d_out;

    dim3 block(NT, 1, 1);
    dim3 grid(W / BX, H / BY, B);
    cspn_kernel<<<grid, block>>>(gw, hn, h0, out);
}

// round 8
// speedup vs baseline: 1.1944x; 1.0193x over previous
#include <cuda_runtime.h>
#include <cstddef>
#include <cstdint>

// CSPN_6468220748336 — vectorized ownership-shift + Q=8 register ring prefetch,
// fine-grained blocks (4 rows/block) to halve the end-of-kernel tail.
// (Resubmit: previous round died on a container infra flake, not a kernel fault.)
// out[b,y,x] = sum_{i,j} gw[b, i*7+j, y+3, x+3] * src[b, y+3-i, x+3-j]
//   src = h0 at (i,j)=(3,3), else hn; zero-padded outside [0,512)^2.

namespace {
constexpr int K  = 7;
constexpr int K2 = 49;
constexpr int B  = 8;
constexpr int H  = 512;
constexpr int W  = 512;
constexpr int WP = 518;
constexpr int PLANE = WP * WP;

constexpr int BX = 128;                // output cols per block
constexpr int BY = 4;                  // output rows per block (1 warp/row)
constexpr int NT = 128;                // 4 warps

constexpr int Q  = 8;                  // prefetch lookahead (taps), ring size

constexpr int TILE_W = 140;            // hn halo cols [X0-3, X0+137)
constexpr int TILE_H = BY + K - 1;     // 10 halo rows [Y0-3, Y0+7)
}

template <int D>
__device__ __forceinline__ void row_compute(
    const float* __restrict__ p0,        // aligned float4 base, tap 0 (this lane)
    const float (*__restrict__ s_hn)[TILE_W],
    const float* __restrict__ h0_row,
    float* __restrict__ out_row,
    int X0, int w, int l)
{
    const int x0 = X0 + 4 * l + D;

    float h0v[4];
    #pragma unroll
    for (int m = 0; m < 4; ++m)
        h0v[m] = (x0 + m < W) ? __ldg(h0_row + x0 + m) : 0.0f;

    float a0 = 0.f, a1 = 0.f, a2 = 0.f, a3 = 0.f;

    // ---- ring prefetch: taps 0..Q-1 in flight before compute starts ----
    float4 gbuf[Q];
    #pragma unroll
    for (int q = 0; q < Q; ++q)
        gbuf[q] = __ldcs(reinterpret_cast<const float4*>(p0 + (size_t)q * PLANE));

    float win[16];

    #pragma unroll
    for (int t = 0; t < K2; ++t) {
        const int i = t / K;
        const int j = t - i * K;

        if (j == 0) {
            // refresh hn window for tap-row i (4 conflict-free LDS.128)
            const int r = w + 6 - i;
            const float4 wa = *reinterpret_cast<const float4*>(&s_hn[r][4 * l]);
            const float4 wb = *reinterpret_cast<const float4*>(&s_hn[r][4 * l + 4]);
            const float4 wc = *reinterpret_cast<const float4*>(&s_hn[r][4 * l + 8]);
            const float4 wd = *reinterpret_cast<const float4*>(&s_hn[r][4 * l + 12]);
            win[0] = wa.x;  win[1] = wa.y;  win[2]  = wa.z;  win[3]  = wa.w;
            win[4] = wb.x;  win[5] = wb.y;  win[6]  = wb.z;  win[7]  = wb.w;
            win[8] = wc.x;  win[9] = wc.y;  win[10] = wc.z;  win[11] = wc.w;
            win[12] = wd.x; win[13] = wd.y; win[14] = wd.z;  win[15] = wd.w;
        }

        const float4 g = gbuf[t % Q];
        if (t + Q < K2)
            gbuf[t % Q] = __ldcs(reinterpret_cast<const float4*>(
                                     p0 + (size_t)(t + Q) * PLANE));

        if (i == 3 && j == 3) {
            a0 = fmaf(g.x, h0v[0], a0);
            a1 = fmaf(g.y, h0v[1], a1);
            a2 = fmaf(g.z, h0v[2], a2);
            a3 = fmaf(g.w, h0v[3], a3);
        } else {
            a0 = fmaf(g.x, win[D + 0 + 6 - j], a0);
            a1 = fmaf(g.y, win[D + 1 + 6 - j], a1);
            a2 = fmaf(g.z, win[D + 2 + 6 - j], a2);
            a3 = fmaf(g.w, win[D + 3 + 6 - j], a3);
        }
    }

    if (x0 + 0 < W) __stcs(out_row + x0 + 0, a0);
    if (x0 + 1 < W) __stcs(out_row + x0 + 1, a1);
    if (x0 + 2 < W) __stcs(out_row + x0 + 2, a2);
    if (x0 + 3 < W) __stcs(out_row + x0 + 3, a3);
}

__global__ __launch_bounds__(NT, 6) void cspn_kernel(
    const float* __restrict__ gw,
    const float* __restrict__ hn,
    const float* __restrict__ h0,
    float* __restrict__ out)
{
    __shared__ __align__(16) float s_hn[TILE_H][TILE_W];

    const int b  = blockIdx.z;
    const int X0 = blockIdx.x * BX;
    const int Y0 = blockIdx.y * BY;
    const int tid = threadIdx.x;
    const int w = tid >> 5;
    const int l = tid & 31;

    // ---- stage hn halo tile (zero-padded) ----
    const float* __restrict__ hn_b = hn + (size_t)b * H * W;
    #pragma unroll
    for (int idx = tid; idx < TILE_H * TILE_W; idx += NT) {
        const int r  = idx / TILE_W;
        const int c  = idx - r * TILE_W;
        const int gy = Y0 - 3 + r;
        const int gx = X0 - 3 + c;
        float v = 0.0f;
        if ((unsigned)gy < (unsigned)H && (unsigned)gx < (unsigned)W)
            v = __ldg(hn_b + (size_t)gy * W + gx);
        s_hn[r][c] = v;
    }
    __syncthreads();

    const int y = Y0 + w;
    const float* __restrict__ gw_b = gw + (size_t)b * K2 * PLANE;
    const float* rowp = gw_b + (size_t)(y + 3) * WP + 3 + X0;
    const int d = (int)((16u - ((uint32_t)(uintptr_t)rowp & 15u)) >> 2) & 3;  // 1 or 3

    const float* p0 = rowp + 4 * l + d;  // 16B-aligned
    const float* h0_row = h0 + ((size_t)b * H + y) * W;
    float* out_row = out + ((size_t)b * H + y) * W;

    if (d == 3)
        row_compute<3>(p0, s_hn, h0_row, out_row, X0, w, l);
    else
        row_compute<1>(p0, s_hn, h0_row, out_row, X0, w, l);

    // ---- left-edge outputs x in [0, d), leftmost blocks only ----
    if (X0 == 0 && l < d) {
        const int xe = l;
        const float h0e = __ldg(h0_row + xe);
        float acc = 0.0f;
        #pragma unroll
        for (int i = 0; i < K; ++i) {
            #pragma unroll
            for (int j = 0; j < K; ++j) {
                const float g = __ldcs(gw_b + (size_t)(i * K + j) * PLANE
                                       + (size_t)(y + 3) * WP + (xe + 3));
                const float v = (i == 3 && j == 3) ? h0e : s_hn[w + 6 - i][xe + 6 - j];
                acc = fmaf(g, v, acc);
            }
        }
        __stcs(out_row + xe, acc);
    }
}

extern "C" void kernel_launch(void* const* d_in, const int* in_sizes, int n_in,
                              void* d_out, int out_size)
{
    const float* gw = (const float*)d_in[0];
    const float* hn = (const float*)d_in[1];
    const float* h0 = (const float*)d_in[2];
    float* out = (float*)d_out;

    dim3 block(NT, 1, 1);
    dim3 grid(W / BX, H / BY, B);
    cspn_kernel<<<grid, block>>>(gw, hn, h0, out);
}